// round 12
// baseline (speedup 1.0000x reference)
#include <cuda_runtime.h>
#include <cuda_bf16.h>
#include <cmath>

#define Dd 128
static const int NN = 20000;
static const int EE = 320000;
static const int BB = 32;
static const int LLn = 625;

#define WPITCH 136
#define APITCH 72
#define WSLOT (2 * 128 * WPITCH)            // ushorts per weight slot (hi+lo)
#define WBYTES (WSLOT * 2)                  // 69632 B
#define ABYTES (2 * 128 * APITCH * 2)       // 36864 B per A chunk buffer (hi+lo)
#define SMEM_E1 (WBYTES + ABYTES)           // 106496 B (2 CTAs/SM)
#define SMEM_E2 (2 * WBYTES + ABYTES)       // 176128 B (K=256 two-A case)
#define SMEM_N  (WBYTES + 2 * ABYTES)       // 143360 B

// ---------------- scratch (device globals) ----------------
// split-bf16 edge tensors: [hi plane | lo plane], plane = EE*128 ushorts
__device__ __align__(16) unsigned short g_EA0[2 * EE * Dd];
__device__ __align__(16) unsigned short g_EA1[2 * EE * Dd];
__device__ __align__(16) unsigned short g_EH [2 * EE * Dd];
__device__ float g_wts [EE];
__device__ float g_norm[EE];
__device__ int   g_eb  [EE];
__device__ float g_X0[NN * Dd], g_X1[NN * Dd];
__device__ float g_XT[3 * NN * Dd];          // Xa | Xb | Xm
__device__ float g_sum[NN * Dd], g_Hu[NN * Dd];
__device__ float g_KV[2 * NN * Dd];          // K | V
__device__ float g_cnt[NN], g_invc[NN];
__device__ float g_Ue[BB * Dd], g_Uu[BB * Dd], g_uw[BB];
__device__ unsigned g_segmax[BB];
__device__ float g_segsum[BB];
__device__ float g_q[BB * Dd];
__device__ unsigned short g_Wsp[12 * WSLOT];

// ---------------- helpers ----------------
__device__ __forceinline__ unsigned encf(float x) {
    unsigned u = __float_as_uint(x);
    return (u & 0x80000000u) ? ~u : (u | 0x80000000u);
}
__device__ __forceinline__ float decf(unsigned v) {
    return (v & 0x80000000u) ? __uint_as_float(v & 0x7fffffffu) : __uint_as_float(~v);
}
__device__ __forceinline__ void red2(float* p, float a, float b) {
    asm volatile("red.global.add.v2.f32 [%0], {%1,%2};" :: "l"(p), "f"(a), "f"(b) : "memory");
}
__device__ __forceinline__ void mma16816(float* c, const unsigned* a, const unsigned* b) {
    asm("mma.sync.aligned.m16n8k16.row.col.f32.bf16.bf16.f32 "
        "{%0,%1,%2,%3}, {%4,%5,%6,%7}, {%8,%9}, {%0,%1,%2,%3};"
        : "+f"(c[0]), "+f"(c[1]), "+f"(c[2]), "+f"(c[3])
        : "r"(a[0]), "r"(a[1]), "r"(a[2]), "r"(a[3]), "r"(b[0]), "r"(b[1]));
}
__device__ __forceinline__ void ldsm4(unsigned* r, unsigned addr) {
    asm volatile("ldmatrix.sync.aligned.m8n8.x4.shared.b16 {%0,%1,%2,%3}, [%4];"
                 : "=r"(r[0]), "=r"(r[1]), "=r"(r[2]), "=r"(r[3]) : "r"(addr));
}
__device__ __forceinline__ void ldsm2t(unsigned* r, unsigned addr) {
    asm volatile("ldmatrix.sync.aligned.m8n8.x2.trans.shared.b16 {%0,%1}, [%2];"
                 : "=r"(r[0]), "=r"(r[1]) : "r"(addr));
}
__device__ __forceinline__ void split2(float x, float y, unsigned& hi, unsigned& lo) {
    unsigned h;
    asm("cvt.rn.bf16x2.f32 %0, %1, %2;" : "=r"(h) : "f"(y), "f"(x));
    float xh = __uint_as_float(h << 16);
    float yh = __uint_as_float(h & 0xffff0000u);
    unsigned l;
    asm("cvt.rn.bf16x2.f32 %0, %1, %2;" : "=r"(l) : "f"(y - yh), "f"(x - xh));
    hi = h; lo = l;
}
__device__ __forceinline__ unsigned cvta_s(const void* p) {
    return (unsigned)__cvta_generic_to_shared(p);
}
__device__ __forceinline__ void cp16(unsigned saddr, const void* g) {
    asm volatile("cp.async.cg.shared.global [%0], [%1], 16;" :: "r"(saddr), "l"(g));
}
__device__ __forceinline__ void cp_commit() { asm volatile("cp.async.commit_group;"); }
__device__ __forceinline__ void cp_wait0() { asm volatile("cp.async.wait_group 0;"); }
__device__ __forceinline__ float gelu1(float v) {
    return 0.5f * v * (1.f + erff(v * 0.70710678118654752440f));
}

// ---- weight prep: W[128,128] fp32 -> bf16 hi/lo padded smem image ----
__global__ void wprepk(const float* __restrict__ W, unsigned short* __restrict__ dst) {
    int k = blockIdx.x;
    int n = threadIdx.x;
    float w = W[k * 128 + n];
    __nv_bfloat16 h = __float2bfloat16(w);
    dst[k * WPITCH + n] = __bfloat16_as_ushort(h);
    dst[128 * WPITCH + k * WPITCH + n] =
        __bfloat16_as_ushort(__float2bfloat16(w - __bfloat162float(h)));
}

// ---- GEMM building blocks ----
__device__ __forceinline__ void copyW(const unsigned short* __restrict__ gW,
                                      unsigned short* sW, int tid) {
    const uint4* s = (const uint4*)gW;
    uint4* d = (uint4*)sW;
#pragma unroll
    for (int i = 0; i < 17; i++) d[tid + 256 * i] = s[tid + 256 * i];
}
// fp32 source stage: load, (rowscale/gelu), split, store
__device__ __forceinline__ void stageA(const float* __restrict__ src, int m0, int M, int kk64,
                                       const float* __restrict__ rs, int dogelu,
                                       unsigned short* sAhi, unsigned short* sAlo, int tid) {
#pragma unroll
    for (int j = 0; j < 8; j++) {
        int f = tid + 256 * j;
        int r = f >> 4, c4 = f & 15;
        int gr = m0 + r;
        float4 v = make_float4(0.f, 0.f, 0.f, 0.f);
        if (gr < M) {
            v = *(const float4*)(src + (size_t)gr * 128 + kk64 + c4 * 4);
            if (rs) { float s = rs[gr]; v.x *= s; v.y *= s; v.z *= s; v.w *= s; }
            if (dogelu) { v.x = gelu1(v.x); v.y = gelu1(v.y); v.z = gelu1(v.z); v.w = gelu1(v.w); }
        }
        unsigned h01, l01, h23, l23;
        split2(v.x, v.y, h01, l01);
        split2(v.z, v.w, h23, l23);
        int off = r * APITCH + c4 * 4;
        *(uint2*)&sAhi[off] = make_uint2(h01, h23);
        *(uint2*)&sAlo[off] = make_uint2(l01, l23);
    }
}
// split source stage: cp.async both planes (issue only; caller waits)
__device__ __forceinline__ void cpstage(const unsigned short* __restrict__ src, size_t ps,
                                        int m0, int M, int kk64,
                                        unsigned short* sAhi, unsigned short* sAlo, int tid) {
#pragma unroll
    for (int j = 0; j < 8; j++) {
        int f = tid + 256 * j;          // 0..2047
        int plane = f >> 10;
        int f2 = f & 1023;
        int r = f2 >> 3, q = f2 & 7;
        int gr = m0 + r;
        unsigned short* d = (plane ? sAlo : sAhi) + r * APITCH + q * 8;
        if (gr < M) {
            cp16(cvta_s(d), src + (size_t)plane * ps + (size_t)gr * 128 + kk64 + q * 8);
        } else {
            *(uint4*)d = make_uint4(0, 0, 0, 0);
        }
    }
    cp_commit();
}
__device__ __forceinline__ void mainloop4(float (&c)[4][4][4],
                                          unsigned aHiB, unsigned aLoB,
                                          unsigned wHiB, unsigned wLoB, int k0g,
                                          int wr, int wc, int arow, int acol, int krow) {
#pragma unroll
    for (int ks = 0; ks < 4; ks++) {
        const int kb = ks * 16;
        unsigned aH[4][4], aL[4][4];
#pragma unroll
        for (int mi = 0; mi < 4; mi++) {
            unsigned off = ((wr + mi * 16 + arow) * APITCH + acol + kb) * 2;
            ldsm4(aH[mi], aHiB + off);
            ldsm4(aL[mi], aLoB + off);
        }
        unsigned bH[4][2], bL[4][2];
#pragma unroll
        for (int ni = 0; ni < 4; ni++) {
            unsigned off = ((k0g + kb + krow) * WPITCH + wc + ni * 8) * 2;
            ldsm2t(bH[ni], wHiB + off);
            ldsm2t(bL[ni], wLoB + off);
        }
#pragma unroll
        for (int mi = 0; mi < 4; mi++)
#pragma unroll
            for (int ni = 0; ni < 4; ni++)
                mma16816(c[mi][ni], aH[mi], bH[ni]);
#pragma unroll
        for (int mi = 0; mi < 4; mi++)
#pragma unroll
            for (int ni = 0; ni < 4; ni++)
                mma16816(c[mi][ni], aH[mi], bL[ni]);
#pragma unroll
        for (int mi = 0; mi < 4; mi++)
#pragma unroll
            for (int ni = 0; ni < 4; ni++)
                mma16816(c[mi][ni], aL[mi], bH[ni]);
    }
}

// ---- persistent edge/general GEMM ----
// A source: fp32 (asplit=0) or split-bf16 planes (asplit=1, pipelined cp.async).
// Output: fp32 (outsplit=0), split planes (outsplit=1), or weighted red-scatter (sIdx).
// Optional fused edge-weight dot: wout[r] += sum(v * Wwv[col]) (4 atomics/row).
__global__ void __launch_bounds__(256, 2) gemmE(
    const void* __restrict__ Ain, int asplit, size_t aps,
    const unsigned short* __restrict__ gW, const float* __restrict__ bias,
    void* __restrict__ Coutv, int outsplit, size_t cps, int M, int ntiles,
    const float* __restrict__ A2, const unsigned short* __restrict__ gW2,
    const float* __restrict__ rs2,
    const float* __restrict__ P1, const int* __restrict__ I1,
    const float* __restrict__ P2, const int* __restrict__ I2,
    const float* __restrict__ P3, const int* __restrict__ I3,
    int relu, const int* __restrict__ sIdx, const float* __restrict__ sScale,
    const float* __restrict__ Wwv, float* __restrict__ wout)
{
    extern __shared__ __align__(16) unsigned short sm[];
    unsigned short* sWhi  = sm;
    unsigned short* sAhi  = sm + 2 * 128 * WPITCH;
    unsigned short* sAlo  = sAhi + 128 * APITCH;
    unsigned short* sW2hi = sAlo + 128 * APITCH;

    const int tid = threadIdx.x, lane = tid & 31, warp = tid >> 5;
    const int wr = (warp >> 2) * 64, wc = (warp & 3) * 32;
    const int arow = (lane & 7) + ((lane >> 3) & 1) * 8;
    const int acol = (lane >> 4) * 8;
    const int krow = lane & 15;
    const int t2 = (lane & 3) * 2, g = lane >> 2;

    copyW(gW, sWhi, tid);
    if (gW2) copyW(gW2, sW2hi, tid);

    const unsigned wHiB = cvta_s(sWhi),  wLoB = wHiB + 128 * WPITCH * 2;
    const unsigned aHiB = cvta_s(sAhi),  aLoB = aHiB + 128 * APITCH * 2;
    const unsigned w2HiB = cvta_s(sW2hi), w2LoB = w2HiB + 128 * WPITCH * 2;
    const int nkt = gW2 ? 4 : 2;
    float* Cout = (float*)Coutv;
    unsigned short* Cs = (unsigned short*)Coutv;
    const unsigned short* Asp = (const unsigned short*)Ain;

    float2 ww[4];
    if (Wwv) {
#pragma unroll
        for (int ni = 0; ni < 4; ni++)
            ww[ni] = *(const float2*)(Wwv + wc + ni * 8 + t2);
    }

    if (asplit) cpstage(Asp, aps, blockIdx.x * 128, M, 0, sAhi, sAlo, tid);

    for (int t = blockIdx.x; t < ntiles; t += gridDim.x) {
        const int m0 = t * 128;
        float c[4][4][4];
#pragma unroll
        for (int mi = 0; mi < 4; mi++)
#pragma unroll
            for (int ni = 0; ni < 4; ni++)
#pragma unroll
                for (int q = 0; q < 4; q++) c[mi][ni][q] = 0.f;

        if (asplit) {
            cp_wait0();
            __syncthreads();
            mainloop4(c, aHiB, aLoB, wHiB, wLoB, 0, wr, wc, arow, acol, krow);
            __syncthreads();
            cpstage(Asp, aps, m0, M, 64, sAhi, sAlo, tid);
            cp_wait0();
            __syncthreads();
            mainloop4(c, aHiB, aLoB, wHiB, wLoB, 64, wr, wc, arow, acol, krow);
            __syncthreads();
            int tn = t + gridDim.x;
            if (tn < ntiles)
                cpstage(Asp, aps, tn * 128, M, 0, sAhi, sAlo, tid);  // overlaps epilogue
        } else {
            for (int kt = 0; kt < nkt; kt++) {
                __syncthreads();
                stageA(kt < 2 ? (const float*)Ain : A2, m0, M, (kt & 1) * 64,
                       kt < 2 ? (const float*)nullptr : rs2, 0, sAhi, sAlo, tid);
                __syncthreads();
                mainloop4(c, aHiB, aLoB, kt < 2 ? wHiB : w2HiB, kt < 2 ? wLoB : w2LoB,
                          (kt & 1) * 64, wr, wc, arow, acol, krow);
            }
        }

        // ---- fused epilogue ----
        float2 bs[4];
#pragma unroll
        for (int ni = 0; ni < 4; ni++)
            bs[ni] = bias ? *(const float2*)(bias + wc + ni * 8 + t2) : make_float2(0.f, 0.f);
#pragma unroll
        for (int mi = 0; mi < 4; mi++) {
#pragma unroll
            for (int half = 0; half < 2; half++) {
                int r = m0 + wr + mi * 16 + g + half * 8;
                if (r >= M) continue;
                int x1 = 0, x2 = 0, x3 = 0;
                if (P1) x1 = I1 ? I1[r] : r;
                if (P2) x2 = I2 ? I2[r] : r;
                if (P3) x3 = I3 ? I3[r] : r;
                float ssc = 0.f; int soff = 0;
                if (sIdx) { ssc = sScale[r]; soff = sIdx[r]; }
                float wacc = 0.f;
#pragma unroll
                for (int ni = 0; ni < 4; ni++) {
                    int col = wc + ni * 8 + t2;
                    float vx = c[mi][ni][half * 2 + 0] + bs[ni].x;
                    float vy = c[mi][ni][half * 2 + 1] + bs[ni].y;
                    if (P1) { float2 p = *(const float2*)(P1 + (size_t)x1 * 128 + col); vx += p.x; vy += p.y; }
                    if (P2) { float2 p = *(const float2*)(P2 + (size_t)x2 * 128 + col); vx += p.x; vy += p.y; }
                    if (P3) { float2 p = *(const float2*)(P3 + (size_t)x3 * 128 + col); vx += p.x; vy += p.y; }
                    if (relu) { vx = fmaxf(vx, 0.f); vy = fmaxf(vy, 0.f); }
                    if (Wwv) wacc += vx * ww[ni].x + vy * ww[ni].y;
                    if (sIdx) {
                        red2(Cout + (size_t)soff * 128 + col, vx * ssc, vy * ssc);
                    } else if (outsplit) {
                        unsigned h, l;
                        split2(vx, vy, h, l);
                        unsigned short* cp = Cs + (size_t)r * 128 + col;
                        *(unsigned*)cp = h;
                        *(unsigned*)(cp + cps) = l;
                    } else {
                        *(float2*)(Cout + (size_t)r * 128 + col) = make_float2(vx, vy);
                    }
                }
                if (Wwv) {
                    wacc += __shfl_xor_sync(0xffffffffu, wacc, 1);
                    wacc += __shfl_xor_sync(0xffffffffu, wacc, 2);
                    if ((lane & 3) == 0)
                        atomicAdd(&wout[r], wacc);
                }
            }
        }
    }
}

// ---- multi-slot node GEMM: stage A once, run S weight slots (fp32 in/out) ----
__global__ void __launch_bounds__(256, 1) gemmN(
    const float* __restrict__ A, const unsigned short* __restrict__ gW,
    const float* __restrict__ b0, const float* __restrict__ b1, const float* __restrict__ b2,
    float* __restrict__ C, size_t cstride, int M, int S, int dogelu)
{
    extern __shared__ __align__(16) unsigned short sm[];
    unsigned short* sWhi  = sm;
    unsigned short* sA0hi = sm + 2 * 128 * WPITCH;
    unsigned short* sA0lo = sA0hi + 128 * APITCH;
    unsigned short* sA1hi = sA0lo + 128 * APITCH;
    unsigned short* sA1lo = sA1hi + 128 * APITCH;

    const int tid = threadIdx.x, lane = tid & 31, warp = tid >> 5;
    const int wr = (warp >> 2) * 64, wc = (warp & 3) * 32;
    const int arow = (lane & 7) + ((lane >> 3) & 1) * 8;
    const int acol = (lane >> 4) * 8;
    const int krow = lane & 15;
    const int t2 = (lane & 3) * 2, g = lane >> 2;
    const int m0 = blockIdx.x * 128;

    stageA(A, m0, M, 0,  nullptr, dogelu, sA0hi, sA0lo, tid);
    stageA(A, m0, M, 64, nullptr, dogelu, sA1hi, sA1lo, tid);

    const unsigned wHiB = cvta_s(sWhi),  wLoB = wHiB + 128 * WPITCH * 2;
    const unsigned a0HiB = cvta_s(sA0hi), a0LoB = a0HiB + 128 * APITCH * 2;
    const unsigned a1HiB = cvta_s(sA1hi), a1LoB = a1HiB + 128 * APITCH * 2;

    for (int s = 0; s < S; s++) {
        __syncthreads();
        copyW(gW + (size_t)s * WSLOT, sWhi, tid);
        __syncthreads();
        float c[4][4][4];
#pragma unroll
        for (int mi = 0; mi < 4; mi++)
#pragma unroll
            for (int ni = 0; ni < 4; ni++)
#pragma unroll
                for (int q = 0; q < 4; q++) c[mi][ni][q] = 0.f;
        mainloop4(c, a0HiB, a0LoB, wHiB, wLoB, 0,  wr, wc, arow, acol, krow);
        mainloop4(c, a1HiB, a1LoB, wHiB, wLoB, 64, wr, wc, arow, acol, krow);

        const float* bias = (s == 0) ? b0 : (s == 1 ? b1 : b2);
        float* Cs = C + (size_t)s * cstride;
        float2 bs[4];
#pragma unroll
        for (int ni = 0; ni < 4; ni++)
            bs[ni] = bias ? *(const float2*)(bias + wc + ni * 8 + t2) : make_float2(0.f, 0.f);
#pragma unroll
        for (int mi = 0; mi < 4; mi++) {
#pragma unroll
            for (int half = 0; half < 2; half++) {
                int r = m0 + wr + mi * 16 + g + half * 8;
                if (r >= M) continue;
#pragma unroll
                for (int ni = 0; ni < 4; ni++) {
                    int col = wc + ni * 8 + t2;
                    *(float2*)(Cs + (size_t)r * 128 + col) =
                        make_float2(c[mi][ni][half * 2 + 0] + bs[ni].x,
                                    c[mi][ni][half * 2 + 1] + bs[ni].y);
                }
            }
        }
    }
}

// ---------------- small kernels ----------------
__global__ void ebk(const int* __restrict__ ei, const int* __restrict__ nb,
                    int* __restrict__ eb, float* __restrict__ cnt, int E, int N) {
    for (int e = blockIdx.x * blockDim.x + threadIdx.x; e < E; e += gridDim.x * blockDim.x) {
        eb[e] = nb[ei[e]];
        if (e < N) cnt[e] = 0.f;
    }
}
__global__ void zerok(float* p, int n) {
    for (int i = blockIdx.x * blockDim.x + threadIdx.x; i < n; i += gridDim.x * blockDim.x)
        p[i] = 0.f;
}
__global__ void cntk(const int* __restrict__ col, float* __restrict__ cnt, int E) {
    for (int e = blockIdx.x * blockDim.x + threadIdx.x; e < E; e += gridDim.x * blockDim.x)
        atomicAdd(&cnt[col[e]], 1.f);
}
__global__ void invk(const float* __restrict__ cnt, float* __restrict__ inv, int N) {
    for (int n = blockIdx.x * blockDim.x + threadIdx.x; n < N; n += gridDim.x * blockDim.x)
        inv[n] = 1.f / fmaxf(cnt[n], 1.f);
}
__global__ void uprepk(const float* __restrict__ u,
                       const float* __restrict__ We1, const float* __restrict__ be1,
                       const float* __restrict__ Wu1,
                       const float* __restrict__ Ww, const float* __restrict__ bw,
                       float* __restrict__ Ue, float* __restrict__ Uu, float* __restrict__ uw) {
    int b = blockIdx.x, tid = threadIdx.x;
    __shared__ float us[128];
    __shared__ float red[128];
    us[tid] = u[b * 128 + tid];
    __syncthreads();
    float aE = be1[tid], aU = 0.f;
    for (int k = 0; k < 128; k++) {
        float uk = us[k];
        aE = fmaf(uk, We1[(384 + k) * 128 + tid], aE);
        aU = fmaf(uk, Wu1[(256 + k) * 128 + tid], aU);
    }
    Ue[b * 128 + tid] = aE;
    Uu[b * 128 + tid] = aU;
    red[tid] = us[tid] * Ww[128 + tid];
    __syncthreads();
    for (int s = 64; s > 0; s >>= 1) { if (tid < s) red[tid] += red[tid + s]; __syncthreads(); }
    if (tid == 0) uw[b] = red[0] + bw[0];
}
__global__ void init32k(unsigned* mx, float* sm) {
    int t = threadIdx.x;
    if (t < 32) { mx[t] = 0u; sm[t] = 0.f; }
}
// layer-0 wts from fp32 edge attr (also seeds segmax)
__global__ void wtsk(const float* __restrict__ EA, const float* __restrict__ Ww,
                     const float* __restrict__ uw, const int* __restrict__ eb,
                     float* __restrict__ wts, unsigned* __restrict__ segmax, int E) {
    __shared__ unsigned smax[32];
    int tid = threadIdx.x, lane = tid & 31, wid = tid >> 5;
    if (tid < 32) smax[tid] = 0u;
    __syncthreads();
    float4 wv = *(const float4*)(Ww + lane * 4);
    int ebase = (blockIdx.x * 8 + wid) * 16;
    for (int t = 0; t < 16; t++) {
        int e = ebase + t;
        if (e >= E) break;
        float4 a = *(const float4*)(EA + (size_t)e * 128 + lane * 4);
        float s = a.x * wv.x + a.y * wv.y + a.z * wv.z + a.w * wv.w;
#pragma unroll
        for (int o = 16; o; o >>= 1) s += __shfl_xor_sync(0xffffffffu, s, o);
        if (lane == 0) {
            int b = eb[e];
            s += uw[b];
            wts[e] = s;
            atomicMax(&smax[b], encf(s));
        }
    }
    __syncthreads();
    if (tid < 32 && smax[tid]) atomicMax(&segmax[tid], smax[tid]);
}
// wts pre-init for fused accumulation: wts[e] = uw[eb[e]]
__global__ void wtsinitk(float* __restrict__ wts, const int* __restrict__ eb,
                         const float* __restrict__ uw, int E) {
    for (int e = blockIdx.x * blockDim.x + threadIdx.x; e < E; e += gridDim.x * blockDim.x)
        wts[e] = uw[eb[e]];
}
// segment max over completed wts (layers 1,2)
__global__ void segmaxk(const float* __restrict__ wts, const int* __restrict__ eb,
                        unsigned* __restrict__ segmax, int E) {
    __shared__ unsigned smax[32];
    int tid = threadIdx.x;
    if (tid < 32) smax[tid] = 0u;
    __syncthreads();
    for (int e = blockIdx.x * blockDim.x + tid; e < E; e += gridDim.x * blockDim.x)
        atomicMax(&smax[eb[e]], encf(wts[e]));
    __syncthreads();
    if (tid < 32 && smax[tid]) atomicMax(&segmax[tid], smax[tid]);
}
__global__ void expsumk(float* __restrict__ wts, const int* __restrict__ eb,
                        const unsigned* __restrict__ segmax, float* __restrict__ segsum, int E) {
    __shared__ float ss[32];
    int tid = threadIdx.x;
    if (tid < 32) ss[tid] = 0.f;
    __syncthreads();
    for (int e = blockIdx.x * blockDim.x + tid; e < E; e += gridDim.x * blockDim.x) {
        int b = eb[e];
        float t = expf(wts[e] - decf(segmax[b]));
        wts[e] = t;
        atomicAdd(&ss[b], t);
    }
    __syncthreads();
    if (tid < 32) atomicAdd(&segsum[tid], ss[tid]);
}
__global__ void normk(const float* __restrict__ wts, const int* __restrict__ eb,
                      const float* __restrict__ segsum, float* __restrict__ nw, int E) {
    for (int e = blockIdx.x * blockDim.x + threadIdx.x; e < E; e += gridDim.x * blockDim.x)
        nw[e] = wts[e] / segsum[eb[e]];
}
// pooled edge from split-bf16 edge attr
__global__ void pooledk(const unsigned short* __restrict__ EAh, size_t ps,
                        const float* __restrict__ nw,
                        const int* __restrict__ eb, float* __restrict__ out, int E) {
    __shared__ float acc[32 * 128];
    int tid = threadIdx.x;
    for (int i = tid; i < 4096; i += 256) acc[i] = 0.f;
    __syncthreads();
    size_t total = (size_t)E * 128;
    for (size_t idx = (size_t)blockIdx.x * 256 + tid; idx < total; idx += (size_t)gridDim.x * 256) {
        int e = (int)(idx >> 7), d = (int)(idx & 127);
        float v = __uint_as_float(((unsigned)EAh[idx]) << 16)
                + __uint_as_float(((unsigned)EAh[ps + idx]) << 16);
        atomicAdd(&acc[eb[e] * 128 + d], v * nw[e]);
    }
    __syncthreads();
    for (int i = tid; i < 4096; i += 256)
        atomicAdd(&out[(i >> 7) * 256 + (i & 127)], acc[i]);
}
__global__ void qk(const float* __restrict__ qa, const float* __restrict__ Wq,
                   const float* __restrict__ bq, float* __restrict__ q) {
    int b = blockIdx.x, tid = threadIdx.x;
    __shared__ float s[1024];
    for (int i = tid; i < 1024; i += 128) s[i] = qa[b * 1024 + i];
    __syncthreads();
    float a = bq[tid];
    for (int k = 0; k < 1024; k++) a = fmaf(s[k], Wq[k * 128 + tid], a);
    q[b * 128 + tid] = a;
}
__global__ void attnk(const float* __restrict__ q, const float* __restrict__ K,
                      const float* __restrict__ V, const int* __restrict__ non,
                      float* __restrict__ out) {
    int b = blockIdx.x >> 1, h = blockIdx.x & 1;
    __shared__ float qs[64];
    __shared__ float sc[LLn];
    __shared__ float red[256];
    int tid = threadIdx.x;
    if (tid < 64) qs[tid] = q[b * 128 + h * 64 + tid];
    __syncthreads();
    int nn = non[b];
    for (int l = tid; l < LLn; l += 256) {
        const float* kp = K + ((size_t)(b * LLn + l)) * 128 + h * 64;
        float s = 0.f;
#pragma unroll
        for (int d = 0; d < 64; d++) s = fmaf(qs[d], kp[d], s);
        s *= 0.125f;
        if (l >= nn) s = -1e30f;
        sc[l] = s;
    }
    __syncthreads();
    float lm = -1e30f;
    for (int l = tid; l < LLn; l += 256) lm = fmaxf(lm, sc[l]);
    red[tid] = lm; __syncthreads();
    for (int s = 128; s > 0; s >>= 1) { if (tid < s) red[tid] = fmaxf(red[tid], red[tid + s]); __syncthreads(); }
    float m = red[0];
    __syncthreads();
    float ls = 0.f;
    for (int l = tid; l < LLn; l += 256) { float t = expf(sc[l] - m); sc[l] = t; ls += t; }
    red[tid] = ls; __syncthreads();
    for (int s = 128; s > 0; s >>= 1) { if (tid < s) red[tid] += red[tid + s]; __syncthreads(); }
    float denom = red[0];
    __syncthreads();
    if (tid < 64) {
        float a = 0.f;
        for (int l = 0; l < LLn; l++)
            a = fmaf(sc[l], V[((size_t)(b * LLn + l)) * 128 + h * 64 + tid], a);
        out[b * 256 + 128 + h * 64 + tid] = a / denom;
    }
}

// ---------------- host ----------------
static unsigned short* g_WspPtr;
static const size_t EPS = (size_t)EE * Dd;

static void gE(const void* A, int asplit, int slot, const float* bias,
               void* C, int outsplit, int M,
               const float* A2, int slot2, const float* rs2,
               const float* P1, const int* I1,
               const float* P2, const int* I2,
               const float* P3, const int* I3,
               int relu, const int* sIdx = nullptr, const float* sScale = nullptr,
               const float* Wwv = nullptr, float* wout = nullptr) {
    int ntiles = (M + 127) / 128;
    int grid = ntiles < 296 ? ntiles : 296;
    size_t smem = A2 ? SMEM_E2 : SMEM_E1;
    gemmE<<<grid, 256, smem>>>(A, asplit, EPS, g_WspPtr + slot * WSLOT, bias,
                               C, outsplit, EPS, M, ntiles,
                               A2, A2 ? g_WspPtr + slot2 * WSLOT : nullptr, rs2,
                               P1, I1, P2, I2, P3, I3, relu, sIdx, sScale, Wwv, wout);
}

#define SYM(p, s) do { void* _q = nullptr; cudaGetSymbolAddress(&_q, s); p = (decltype(p))_q; } while (0)

extern "C" void kernel_launch(void* const* d_in, const int* in_sizes, int n_in,
                              void* d_out, int out_size) {
    cudaFuncSetAttribute(gemmE, cudaFuncAttributeMaxDynamicSharedMemorySize, SMEM_E2);
    cudaFuncSetAttribute(gemmN, cudaFuncAttributeMaxDynamicSharedMemorySize, SMEM_N);

    const float* x_in  = (const float*)d_in[0];
    const float* ea_in = (const float*)d_in[1];
    const float* u_in  = (const float*)d_in[2];
    const float* qa_in = (const float*)d_in[3];
    const float* W_e1  = (const float*)d_in[4];
    const float* b_e1  = (const float*)d_in[5];
    const float* W_e2  = (const float*)d_in[6];
    const float* b_e2  = (const float*)d_in[7];
    const float* W_w   = (const float*)d_in[8];
    const float* b_w   = (const float*)d_in[9];
    const float* W_m1  = (const float*)d_in[10];
    const float* b_m1  = (const float*)d_in[11];
    const float* W_m2  = (const float*)d_in[12];
    const float* b_m2  = (const float*)d_in[13];
    const float* W_u1  = (const float*)d_in[14];
    const float* b_u1  = (const float*)d_in[15];
    const float* W_u2  = (const float*)d_in[16];
    const float* b_u2  = (const float*)d_in[17];
    const float* W_q   = (const float*)d_in[18];
    const float* b_q   = (const float*)d_in[19];
    const float* W_k   = (const float*)d_in[20];
    const float* b_k   = (const float*)d_in[21];
    const float* W_v   = (const float*)d_in[22];
    const float* b_v   = (const float*)d_in[23];
    const int*   ei    = (const int*)d_in[24];
    const int*   nb    = (const int*)d_in[25];
    const int*   non   = (const int*)d_in[26];
    float* out = (float*)d_out;

    const int* rowI = ei;
    const int* colI = ei + EE;

    unsigned short *EA0, *EA1, *EH;
    float *wts, *nw, *X0, *X1, *XT, *sum, *Hu, *KV;
    float *cnt, *invc, *Ue, *Uu, *uw, *segsum, *qbuf;
    unsigned* segmax; int* eb;
    SYM(EA0, g_EA0); SYM(EA1, g_EA1); SYM(EH, g_EH);
    SYM(wts, g_wts); SYM(nw, g_norm); SYM(eb, g_eb);
    SYM(X0, g_X0); SYM(X1, g_X1); SYM(XT, g_XT);
    SYM(sum, g_sum); SYM(Hu, g_Hu); SYM(KV, g_KV);
    SYM(cnt, g_cnt); SYM(invc, g_invc);
    SYM(Ue, g_Ue); SYM(Uu, g_Uu); SYM(uw, g_uw);
    SYM(segmax, g_segmax); SYM(segsum, g_segsum); SYM(qbuf, g_q);
    SYM(g_WspPtr, g_Wsp);

    const size_t NPS = (size_t)NN * Dd;
    float* Xa = XT;
    float* Xb = XT + NPS;
    float* Xm = XT + 2 * NPS;

    // slot map: 0 We1a 1 We1b 2 Wm1a | 3 We1c 4 We2 5 Wm1b 6 Wm2 7 Wu1a 8 Wu1b 9 Wu2 10 Wk 11 Wv
    wprepk<<<128, 128>>>(W_e1,             g_WspPtr + 0 * WSLOT);  // 1
    wprepk<<<128, 128>>>(W_e1 + 128 * 128, g_WspPtr + 1 * WSLOT);  // 2
    wprepk<<<128, 128>>>(W_m1,             g_WspPtr + 2 * WSLOT);  // 3
    gemmN<<<(NN + 127) / 128, 256, SMEM_N>>>(x_in, g_WspPtr, nullptr, nullptr, nullptr,
                                             XT, NPS, NN, 3, 0);   // 4 (profiled)
    ebk<<<1250, 256>>>(ei, nb, eb, cnt, EE, NN);
    cntk<<<1250, 256>>>(colI, cnt, EE);
    invk<<<79, 256>>>(cnt, invc, NN);
    uprepk<<<BB, 128>>>(u_in, W_e1, b_e1, W_u1, W_w, b_w, Ue, Uu, uw);
    wprepk<<<128, 128>>>(W_e1 + 256 * 128, g_WspPtr + 3 * WSLOT);
    wprepk<<<128, 128>>>(W_e2,             g_WspPtr + 4 * WSLOT);
    wprepk<<<128, 128>>>(W_m1 + 128 * 128, g_WspPtr + 5 * WSLOT);
    wprepk<<<128, 128>>>(W_m2,             g_WspPtr + 6 * WSLOT);
    wprepk<<<128, 128>>>(W_u1,             g_WspPtr + 7 * WSLOT);
    wprepk<<<128, 128>>>(W_u1 + 128 * 128, g_WspPtr + 8 * WSLOT);
    wprepk<<<128, 128>>>(W_u2,             g_WspPtr + 9 * WSLOT);
    wprepk<<<128, 128>>>(W_k,              g_WspPtr + 10 * WSLOT);
    wprepk<<<128, 128>>>(W_v,              g_WspPtr + 11 * WSLOT);

    const float* xCur = x_in;
    float* xBuf[2] = {X0, X1};
    unsigned short* eaCur = nullptr;    // split (layers 1+); layer0 uses ea_in fp32
    unsigned short* eaBuf[2] = {EA0, EA1};

    for (int layer = 0; layer < 3; layer++) {
        unsigned short* eaNxt = eaBuf[layer & 1];
        float* xNxt = xBuf[layer & 1];
        if (layer > 0)
            gemmN<<<(NN + 127) / 128, 256, SMEM_N>>>(xCur, g_WspPtr, nullptr, nullptr, nullptr,
                                                     XT, NPS, NN, 3, 0);
        // segment softmax of edge weights (wts: layer0 computed here; layers1+ fused)
        init32k<<<1, 32>>>(segmax, segsum);
        if (layer == 0)
            wtsk<<<EE / 128, 256>>>(ea_in, W_w, uw, eb, wts, segmax, EE);
        else
            segmaxk<<<640, 256>>>(wts, eb, segmax, EE);
        expsumk<<<640, 256>>>(wts, eb, segmax, segsum, EE);
        normk<<<1250, 256>>>(wts, eb, segsum, nw, EE);
        if (layer < 2)
            wtsinitk<<<1250, 256>>>(wts, eb, uw, EE);   // seed next layer's wts
        // edge MLP1 (b_e1 folded into Ue): EH = relu(EA@We1c + Xa[row]+Xb[col]+Ue[eb])
        if (layer == 0)
            gE(ea_in, 0, 3, nullptr, EH, 1, EE, 0, 0, 0, Xa, rowI, Xb, colI, Ue, eb, 1);
        else
            gE(eaCur, 1, 3, nullptr, EH, 1, EE, 0, 0, 0, Xa, rowI, Xb, colI, Ue, eb, 1);
        // edge MLP2: eaNxt = EH@We2 + b_e2   (+ fused wts dot for next layer)
        gE(EH, 1, 4, b_e2, eaNxt, 1, EE, 0, 0, 0, 0, 0, 0, 0, 0, 0, 0, 0, 0,
           layer < 2 ? W_w : nullptr, layer < 2 ? wts : nullptr);
        // msg MLP1: EH = relu(eaNxt@Wm1b + Xm[row] + b_m1)
        gE(eaNxt, 1, 5, b_m1, EH, 1, EE, 0, 0, 0, Xm, rowI, 0, 0, 0, 0, 1);
        // msg MLP2 + weighted scatter over col
        zerok<<<4096, 256>>>(sum, NN * Dd);
        gE(EH, 1, 6, b_m2, sum, 0, EE, 0, 0, 0, 0, 0, 0, 0, 0, 0, 0, colI, nw);
        // node update: Hu = relu(x@Wu1a + (sum*invc)@Wu1b + Uu[nb] + b_u1)
        gE(xCur, 0, 7, b_u1, Hu, 0, NN, sum, 8, invc, Uu, nb, 0, 0, 0, 0, 1);
        gE(Hu, 0, 9, b_u2, xNxt, 0, NN, 0, 0, 0, 0, 0, 0, 0, 0, 0, 0);
        eaCur = eaNxt;
        xCur = xNxt;
    }

    // outputs
    zerok<<<32, 256>>>(out, BB * 256);
    pooledk<<<640, 256>>>(eaCur, EPS, nw, eb, out, EE);
    // K,V = gelu(x) @ {W_k, W_v} + {b_k, b_v}
    gemmN<<<(NN + 127) / 128, 256, SMEM_N>>>(xCur, g_WspPtr + 10 * WSLOT, b_k, b_v, nullptr,
                                             KV, NPS, NN, 2, 1);
    qk<<<BB, 128>>>(qa_in, W_q, b_q, qbuf);
    attnk<<<BB * 2, 256>>>(qbuf, KV, KV + NPS, non, out);
}

// round 13
// speedup vs baseline: 1.1171x; 1.1171x over previous
#include <cuda_runtime.h>
#include <cuda_bf16.h>
#include <cmath>

#define Dd 128
static const int NN = 20000;
static const int EE = 320000;
static const int BB = 32;
static const int LLn = 625;

#define WPITCH 136
#define APITCH 72      // gemmN (64-col chunks)
#define CPITCH 40      // gemmE (32-col chunks)
#define WSLOT (2 * 128 * WPITCH)            // ushorts per weight slot (hi+lo)
#define WBYTES (WSLOT * 2)                  // 69632 B
// gemmE smem: W (69632) + bf16 A chunk (2*128*40*2 = 20480) + fp32 stage (16384)
#define SMEM_E1 (WBYTES + 20480 + 16384)    // 106496 B -> 2 CTAs/SM
#define SMEM_E2 (SMEM_E1 + WBYTES)          // 176128 B (K=256 two-W case)
#define SMEM_N  (WBYTES + 2 * (2 * 128 * APITCH * 2))  // 143360 B

// ---------------- scratch (device globals) ----------------
__device__ float g_EA0[EE * Dd];
__device__ float g_EA1[EE * Dd];
__device__ float g_EH [EE * Dd];
__device__ float g_wts [EE];
__device__ float g_norm[EE];
__device__ int   g_eb  [EE];
__device__ float g_X0[NN * Dd], g_X1[NN * Dd];
__device__ float g_XT[3 * NN * Dd];          // Xa | Xb | Xm
__device__ float g_sum[NN * Dd], g_Hu[NN * Dd];
__device__ float g_KV[2 * NN * Dd];          // K | V
__device__ float g_cnt[NN], g_invc[NN];
__device__ float g_Ue[BB * Dd], g_Uu[BB * Dd], g_uw[BB];
__device__ unsigned g_segmax[BB];
__device__ float g_segsum[BB];
__device__ float g_q[BB * Dd];
__device__ unsigned short g_Wsp[12 * WSLOT];

// ---------------- helpers ----------------
__device__ __forceinline__ unsigned encf(float x) {
    unsigned u = __float_as_uint(x);
    return (u & 0x80000000u) ? ~u : (u | 0x80000000u);
}
__device__ __forceinline__ float decf(unsigned v) {
    return (v & 0x80000000u) ? __uint_as_float(v & 0x7fffffffu) : __uint_as_float(~v);
}
__device__ __forceinline__ void red2(float* p, float a, float b) {
    asm volatile("red.global.add.v2.f32 [%0], {%1,%2};" :: "l"(p), "f"(a), "f"(b) : "memory");
}
__device__ __forceinline__ void mma16816(float* c, const unsigned* a, const unsigned* b) {
    asm("mma.sync.aligned.m16n8k16.row.col.f32.bf16.bf16.f32 "
        "{%0,%1,%2,%3}, {%4,%5,%6,%7}, {%8,%9}, {%0,%1,%2,%3};"
        : "+f"(c[0]), "+f"(c[1]), "+f"(c[2]), "+f"(c[3])
        : "r"(a[0]), "r"(a[1]), "r"(a[2]), "r"(a[3]), "r"(b[0]), "r"(b[1]));
}
__device__ __forceinline__ void ldsm4(unsigned* r, unsigned addr) {
    asm volatile("ldmatrix.sync.aligned.m8n8.x4.shared.b16 {%0,%1,%2,%3}, [%4];"
                 : "=r"(r[0]), "=r"(r[1]), "=r"(r[2]), "=r"(r[3]) : "r"(addr));
}
__device__ __forceinline__ void ldsm2t(unsigned* r, unsigned addr) {
    asm volatile("ldmatrix.sync.aligned.m8n8.x2.trans.shared.b16 {%0,%1}, [%2];"
                 : "=r"(r[0]), "=r"(r[1]) : "r"(addr));
}
__device__ __forceinline__ void split2(float x, float y, unsigned& hi, unsigned& lo) {
    unsigned h;
    asm("cvt.rn.bf16x2.f32 %0, %1, %2;" : "=r"(h) : "f"(y), "f"(x));
    float xh = __uint_as_float(h << 16);
    float yh = __uint_as_float(h & 0xffff0000u);
    unsigned l;
    asm("cvt.rn.bf16x2.f32 %0, %1, %2;" : "=r"(l) : "f"(y - yh), "f"(x - xh));
    hi = h; lo = l;
}
__device__ __forceinline__ unsigned cvta_s(const void* p) {
    return (unsigned)__cvta_generic_to_shared(p);
}
__device__ __forceinline__ void cp16(unsigned saddr, const void* g) {
    asm volatile("cp.async.cg.shared.global [%0], [%1], 16;" :: "r"(saddr), "l"(g));
}
__device__ __forceinline__ void cp_commit() { asm volatile("cp.async.commit_group;"); }
__device__ __forceinline__ void cp_wait0() { asm volatile("cp.async.wait_group 0;"); }
__device__ __forceinline__ float gelu1(float v) {
    return 0.5f * v * (1.f + erff(v * 0.70710678118654752440f));
}

// ---- weight prep: W[128,128] fp32 -> bf16 hi/lo padded smem image ----
__global__ void wprepk(const float* __restrict__ W, unsigned short* __restrict__ dst) {
    int k = blockIdx.x;
    int n = threadIdx.x;
    float w = W[k * 128 + n];
    __nv_bfloat16 h = __float2bfloat16(w);
    dst[k * WPITCH + n] = __bfloat16_as_ushort(h);
    dst[128 * WPITCH + k * WPITCH + n] =
        __bfloat16_as_ushort(__float2bfloat16(w - __bfloat162float(h)));
}

// ---- GEMM building blocks ----
__device__ __forceinline__ void copyW(const unsigned short* __restrict__ gW,
                                      unsigned short* sW, int tid) {
    const uint4* s = (const uint4*)gW;
    uint4* d = (uint4*)sW;
#pragma unroll
    for (int i = 0; i < 17; i++) d[tid + 256 * i] = s[tid + 256 * i];
}
// fp32 direct stage (gemmN; 64-col chunk, APITCH)
__device__ __forceinline__ void stageA(const float* __restrict__ src, int m0, int M, int kk64,
                                       const float* __restrict__ rs, int dogelu,
                                       unsigned short* sAhi, unsigned short* sAlo, int tid) {
#pragma unroll
    for (int j = 0; j < 8; j++) {
        int f = tid + 256 * j;
        int r = f >> 4, c4 = f & 15;
        int gr = m0 + r;
        float4 v = make_float4(0.f, 0.f, 0.f, 0.f);
        if (gr < M) {
            v = *(const float4*)(src + (size_t)gr * 128 + kk64 + c4 * 4);
            if (rs) { float s = rs[gr]; v.x *= s; v.y *= s; v.z *= s; v.w *= s; }
            if (dogelu) { v.x = gelu1(v.x); v.y = gelu1(v.y); v.z = gelu1(v.z); v.w = gelu1(v.w); }
        }
        unsigned h01, l01, h23, l23;
        split2(v.x, v.y, h01, l01);
        split2(v.z, v.w, h23, l23);
        int off = r * APITCH + c4 * 4;
        *(uint2*)&sAhi[off] = make_uint2(h01, h23);
        *(uint2*)&sAlo[off] = make_uint2(l01, l23);
    }
}
// cp.async issue: fp32 32-col chunk -> fstage (128x32 fp32, row pitch 32)
__device__ __forceinline__ void cpissue32(const float* __restrict__ src, int m0, int M,
                                          int col0, float* fstage, int tid) {
#pragma unroll
    for (int j = 0; j < 4; j++) {
        int idx = tid + 256 * j;          // 0..1023 float4s
        int r = idx >> 3, q = idx & 7;
        int gr = m0 + r;
        float* d = fstage + r * 32 + q * 4;
        if (gr < M) cp16(cvta_s(d), src + (size_t)gr * 128 + col0 + q * 4);
        else *(float4*)d = make_float4(0.f, 0.f, 0.f, 0.f);
    }
    cp_commit();
}
// split pass: fstage -> bf16 hi/lo chunk buffer (CPITCH)
__device__ __forceinline__ void split32(const float* __restrict__ fstage,
                                        const float* __restrict__ rs, int m0, int M,
                                        unsigned short* sAhi, unsigned short* sAlo, int tid) {
#pragma unroll
    for (int j = 0; j < 4; j++) {
        int idx = tid + 256 * j;
        int r = idx >> 3, q = idx & 7;
        float4 v = *(const float4*)(fstage + r * 32 + q * 4);
        if (rs) {
            int gr = m0 + r;
            float s = (gr < M) ? rs[gr] : 0.f;
            v.x *= s; v.y *= s; v.z *= s; v.w *= s;
        }
        unsigned h01, l01, h23, l23;
        split2(v.x, v.y, h01, l01);
        split2(v.z, v.w, h23, l23);
        int off = r * CPITCH + q * 4;
        *(uint2*)&sAhi[off] = make_uint2(h01, h23);
        *(uint2*)&sAlo[off] = make_uint2(l01, l23);
    }
}
// mainloop over a 64-col chunk (gemmN, APITCH)
__device__ __forceinline__ void mainloop4(float (&c)[4][4][4],
                                          unsigned aHiB, unsigned aLoB,
                                          unsigned wHiB, unsigned wLoB, int k0g,
                                          int wr, int wc, int arow, int acol, int krow) {
#pragma unroll
    for (int ks = 0; ks < 4; ks++) {
        const int kb = ks * 16;
        unsigned aH[4][4], aL[4][4];
#pragma unroll
        for (int mi = 0; mi < 4; mi++) {
            unsigned off = ((wr + mi * 16 + arow) * APITCH + acol + kb) * 2;
            ldsm4(aH[mi], aHiB + off);
            ldsm4(aL[mi], aLoB + off);
        }
        unsigned bH[4][2], bL[4][2];
#pragma unroll
        for (int ni = 0; ni < 4; ni++) {
            unsigned off = ((k0g + kb + krow) * WPITCH + wc + ni * 8) * 2;
            ldsm2t(bH[ni], wHiB + off);
            ldsm2t(bL[ni], wLoB + off);
        }
#pragma unroll
        for (int mi = 0; mi < 4; mi++)
#pragma unroll
            for (int ni = 0; ni < 4; ni++)
                mma16816(c[mi][ni], aH[mi], bH[ni]);
#pragma unroll
        for (int mi = 0; mi < 4; mi++)
#pragma unroll
            for (int ni = 0; ni < 4; ni++)
                mma16816(c[mi][ni], aH[mi], bL[ni]);
#pragma unroll
        for (int mi = 0; mi < 4; mi++)
#pragma unroll
            for (int ni = 0; ni < 4; ni++)
                mma16816(c[mi][ni], aL[mi], bH[ni]);
    }
}
// mainloop over a 32-col chunk (gemmE, CPITCH); W row base k0w
__device__ __forceinline__ void mainloop2(float (&c)[4][4][4],
                                          unsigned aHiB, unsigned aLoB,
                                          unsigned wHiB, unsigned wLoB, int k0w,
                                          int wr, int wc, int arow, int acol, int krow) {
#pragma unroll
    for (int ks = 0; ks < 2; ks++) {
        const int kb = ks * 16;
        unsigned aH[4][4], aL[4][4];
#pragma unroll
        for (int mi = 0; mi < 4; mi++) {
            unsigned off = ((wr + mi * 16 + arow) * CPITCH + acol + kb) * 2;
            ldsm4(aH[mi], aHiB + off);
            ldsm4(aL[mi], aLoB + off);
        }
        unsigned bH[4][2], bL[4][2];
#pragma unroll
        for (int ni = 0; ni < 4; ni++) {
            unsigned off = ((k0w + kb + krow) * WPITCH + wc + ni * 8) * 2;
            ldsm2t(bH[ni], wHiB + off);
            ldsm2t(bL[ni], wLoB + off);
        }
#pragma unroll
        for (int mi = 0; mi < 4; mi++)
#pragma unroll
            for (int ni = 0; ni < 4; ni++)
                mma16816(c[mi][ni], aH[mi], bH[ni]);
#pragma unroll
        for (int mi = 0; mi < 4; mi++)
#pragma unroll
            for (int ni = 0; ni < 4; ni++)
                mma16816(c[mi][ni], aH[mi], bL[ni]);
#pragma unroll
        for (int mi = 0; mi < 4; mi++)
#pragma unroll
            for (int ni = 0; ni < 4; ni++)
                mma16816(c[mi][ni], aL[mi], bH[ni]);
    }
}

// ---- persistent edge/general GEMM with cp.async-pipelined fp32 staging ----
__global__ void __launch_bounds__(256, 2) gemmE(
    const float* __restrict__ A, const unsigned short* __restrict__ gW,
    const float* __restrict__ bias, float* __restrict__ Cout, int M, int ntiles,
    const float* __restrict__ A2, const unsigned short* __restrict__ gW2,
    const float* __restrict__ rs2,
    const float* __restrict__ P1, const int* __restrict__ I1,
    const float* __restrict__ P2, const int* __restrict__ I2,
    const float* __restrict__ P3, const int* __restrict__ I3,
    int relu, const int* __restrict__ sIdx, const float* __restrict__ sScale)
{
    extern __shared__ __align__(16) unsigned short sm[];
    unsigned short* sWhi = sm;                           // 2*128*WPITCH ushorts
    unsigned short* sAhi = sm + 2 * 128 * WPITCH;        // 128*CPITCH
    unsigned short* sAlo = sAhi + 128 * CPITCH;
    float* fstage = (float*)(sAlo + 128 * CPITCH);       // 128*32 fp32
    unsigned short* sW2hi = (unsigned short*)(fstage + 128 * 32);

    const int tid = threadIdx.x, lane = tid & 31, warp = tid >> 5;
    const int wr = (warp >> 2) * 64, wc = (warp & 3) * 32;
    const int arow = (lane & 7) + ((lane >> 3) & 1) * 8;
    const int acol = (lane >> 4) * 8;
    const int krow = lane & 15;
    const int t2 = (lane & 3) * 2, g = lane >> 2;

    copyW(gW, sWhi, tid);
    if (gW2) copyW(gW2, sW2hi, tid);

    const unsigned wHiB = cvta_s(sWhi),  wLoB = wHiB + 128 * WPITCH * 2;
    const unsigned aHiB = cvta_s(sAhi),  aLoB = cvta_s(sAlo);
    const unsigned w2HiB = cvta_s(sW2hi), w2LoB = w2HiB + 128 * WPITCH * 2;
    const int NC = gW2 ? 8 : 4;    // 32-col chunks (K=128 or K=256)

    // prime pipeline: chunk 0 of first tile
    if (blockIdx.x < ntiles)
        cpissue32(A, blockIdx.x * 128, M, 0, fstage, tid);

    for (int t = blockIdx.x; t < ntiles; t += gridDim.x) {
        const int m0 = t * 128;
        float c[4][4][4];
#pragma unroll
        for (int mi = 0; mi < 4; mi++)
#pragma unroll
            for (int ni = 0; ni < 4; ni++)
#pragma unroll
                for (int q = 0; q < 4; q++) c[mi][ni][q] = 0.f;

        for (int kc = 0; kc < NC; kc++) {
            cp_wait0();
            __syncthreads();   // fstage ready; prior mainloop reads of sA done
            split32(fstage, kc < 4 ? (const float*)nullptr : rs2, m0, M, sAhi, sAlo, tid);
            __syncthreads();   // sA visible; fstage reads done
            // issue next chunk (overlaps this chunk's mainloop / tile epilogue)
            int kn = kc + 1;
            if (kn < NC) {
                cpissue32(kn < 4 ? A : A2, m0, M, (kn & 3) * 32, fstage, tid);
            } else {
                int tn = t + gridDim.x;
                if (tn < ntiles) cpissue32(A, tn * 128, M, 0, fstage, tid);
            }
            if (kc < 4)
                mainloop2(c, aHiB, aLoB, wHiB, wLoB, kc * 32, wr, wc, arow, acol, krow);
            else
                mainloop2(c, aHiB, aLoB, w2HiB, w2LoB, (kc - 4) * 32, wr, wc, arow, acol, krow);
        }

        // ---- fused epilogue ----
        float2 bs[4];
#pragma unroll
        for (int ni = 0; ni < 4; ni++)
            bs[ni] = bias ? *(const float2*)(bias + wc + ni * 8 + t2) : make_float2(0.f, 0.f);
#pragma unroll
        for (int mi = 0; mi < 4; mi++) {
#pragma unroll
            for (int half = 0; half < 2; half++) {
                int r = m0 + wr + mi * 16 + g + half * 8;
                if (r >= M) continue;
                int x1 = 0, x2 = 0, x3 = 0;
                if (P1) x1 = I1 ? I1[r] : r;
                if (P2) x2 = I2 ? I2[r] : r;
                if (P3) x3 = I3 ? I3[r] : r;
                float ssc = 0.f; int soff = 0;
                if (sIdx) { ssc = sScale[r]; soff = sIdx[r]; }
#pragma unroll
                for (int ni = 0; ni < 4; ni++) {
                    int col = wc + ni * 8 + t2;
                    float vx = c[mi][ni][half * 2 + 0] + bs[ni].x;
                    float vy = c[mi][ni][half * 2 + 1] + bs[ni].y;
                    if (P1) { float2 p = *(const float2*)(P1 + (size_t)x1 * 128 + col); vx += p.x; vy += p.y; }
                    if (P2) { float2 p = *(const float2*)(P2 + (size_t)x2 * 128 + col); vx += p.x; vy += p.y; }
                    if (P3) { float2 p = *(const float2*)(P3 + (size_t)x3 * 128 + col); vx += p.x; vy += p.y; }
                    if (relu) { vx = fmaxf(vx, 0.f); vy = fmaxf(vy, 0.f); }
                    if (sIdx) red2(Cout + (size_t)soff * 128 + col, vx * ssc, vy * ssc);
                    else *(float2*)(Cout + (size_t)r * 128 + col) = make_float2(vx, vy);
                }
            }
        }
    }
}

// ---- multi-slot node GEMM: stage A once, run S weight slots ----
__global__ void __launch_bounds__(256, 1) gemmN(
    const float* __restrict__ A, const unsigned short* __restrict__ gW,
    const float* __restrict__ b0, const float* __restrict__ b1, const float* __restrict__ b2,
    float* __restrict__ C, size_t cstride, int M, int S, int dogelu)
{
    extern __shared__ __align__(16) unsigned short sm[];
    unsigned short* sWhi  = sm;
    unsigned short* sA0hi = sm + 2 * 128 * WPITCH;
    unsigned short* sA0lo = sA0hi + 128 * APITCH;
    unsigned short* sA1hi = sA0lo + 128 * APITCH;
    unsigned short* sA1lo = sA1hi + 128 * APITCH;

    const int tid = threadIdx.x, lane = tid & 31, warp = tid >> 5;
    const int wr = (warp >> 2) * 64, wc = (warp & 3) * 32;
    const int arow = (lane & 7) + ((lane >> 3) & 1) * 8;
    const int acol = (lane >> 4) * 8;
    const int krow = lane & 15;
    const int t2 = (lane & 3) * 2, g = lane >> 2;
    const int m0 = blockIdx.x * 128;

    stageA(A, m0, M, 0,  nullptr, dogelu, sA0hi, sA0lo, tid);
    stageA(A, m0, M, 64, nullptr, dogelu, sA1hi, sA1lo, tid);

    const unsigned wHiB = cvta_s(sWhi),  wLoB = wHiB + 128 * WPITCH * 2;
    const unsigned a0HiB = cvta_s(sA0hi), a0LoB = a0HiB + 128 * APITCH * 2;
    const unsigned a1HiB = cvta_s(sA1hi), a1LoB = a1HiB + 128 * APITCH * 2;

    for (int s = 0; s < S; s++) {
        __syncthreads();
        copyW(gW + (size_t)s * WSLOT, sWhi, tid);
        __syncthreads();
        float c[4][4][4];
#pragma unroll
        for (int mi = 0; mi < 4; mi++)
#pragma unroll
            for (int ni = 0; ni < 4; ni++)
#pragma unroll
                for (int q = 0; q < 4; q++) c[mi][ni][q] = 0.f;
        mainloop4(c, a0HiB, a0LoB, wHiB, wLoB, 0,  wr, wc, arow, acol, krow);
        mainloop4(c, a1HiB, a1LoB, wHiB, wLoB, 64, wr, wc, arow, acol, krow);

        const float* bias = (s == 0) ? b0 : (s == 1 ? b1 : b2);
        float* Cs = C + (size_t)s * cstride;
        float2 bs[4];
#pragma unroll
        for (int ni = 0; ni < 4; ni++)
            bs[ni] = bias ? *(const float2*)(bias + wc + ni * 8 + t2) : make_float2(0.f, 0.f);
#pragma unroll
        for (int mi = 0; mi < 4; mi++) {
#pragma unroll
            for (int half = 0; half < 2; half++) {
                int r = m0 + wr + mi * 16 + g + half * 8;
                if (r >= M) continue;
#pragma unroll
                for (int ni = 0; ni < 4; ni++) {
                    int col = wc + ni * 8 + t2;
                    *(float2*)(Cs + (size_t)r * 128 + col) =
                        make_float2(c[mi][ni][half * 2 + 0] + bs[ni].x,
                                    c[mi][ni][half * 2 + 1] + bs[ni].y);
                }
            }
        }
    }
}

// ---------------- small kernels ----------------
__global__ void ebk(const int* __restrict__ ei, const int* __restrict__ nb,
                    int* __restrict__ eb, float* __restrict__ cnt, int E, int N) {
    for (int e = blockIdx.x * blockDim.x + threadIdx.x; e < E; e += gridDim.x * blockDim.x) {
        eb[e] = nb[ei[e]];
        if (e < N) cnt[e] = 0.f;
    }
}
__global__ void zerok(float* p, int n) {
    for (int i = blockIdx.x * blockDim.x + threadIdx.x; i < n; i += gridDim.x * blockDim.x)
        p[i] = 0.f;
}
__global__ void cntk(const int* __restrict__ col, float* __restrict__ cnt, int E) {
    for (int e = blockIdx.x * blockDim.x + threadIdx.x; e < E; e += gridDim.x * blockDim.x)
        atomicAdd(&cnt[col[e]], 1.f);
}
__global__ void invk(const float* __restrict__ cnt, float* __restrict__ inv, int N) {
    for (int n = blockIdx.x * blockDim.x + threadIdx.x; n < N; n += gridDim.x * blockDim.x)
        inv[n] = 1.f / fmaxf(cnt[n], 1.f);
}
__global__ void uprepk(const float* __restrict__ u,
                       const float* __restrict__ We1, const float* __restrict__ be1,
                       const float* __restrict__ Wu1,
                       const float* __restrict__ Ww, const float* __restrict__ bw,
                       float* __restrict__ Ue, float* __restrict__ Uu, float* __restrict__ uw) {
    int b = blockIdx.x, tid = threadIdx.x;
    __shared__ float us[128];
    __shared__ float red[128];
    us[tid] = u[b * 128 + tid];
    __syncthreads();
    float aE = be1[tid], aU = 0.f;
    for (int k = 0; k < 128; k++) {
        float uk = us[k];
        aE = fmaf(uk, We1[(384 + k) * 128 + tid], aE);
        aU = fmaf(uk, Wu1[(256 + k) * 128 + tid], aU);
    }
    Ue[b * 128 + tid] = aE;
    Uu[b * 128 + tid] = aU;
    red[tid] = us[tid] * Ww[128 + tid];
    __syncthreads();
    for (int s = 64; s > 0; s >>= 1) { if (tid < s) red[tid] += red[tid + s]; __syncthreads(); }
    if (tid == 0) uw[b] = red[0] + bw[0];
}
__global__ void init32k(unsigned* mx, float* sm) {
    int t = threadIdx.x;
    if (t < 32) { mx[t] = 0u; sm[t] = 0.f; }
}
__global__ void wtsk(const float* __restrict__ EA, const float* __restrict__ Ww,
                     const float* __restrict__ uw, const int* __restrict__ eb,
                     float* __restrict__ wts, unsigned* __restrict__ segmax, int E) {
    __shared__ unsigned smax[32];
    int tid = threadIdx.x, lane = tid & 31, wid = tid >> 5;
    if (tid < 32) smax[tid] = 0u;
    __syncthreads();
    float4 wv = *(const float4*)(Ww + lane * 4);
    int ebase = (blockIdx.x * 8 + wid) * 16;
    for (int t = 0; t < 16; t++) {
        int e = ebase + t;
        if (e >= E) break;
        float4 a = *(const float4*)(EA + (size_t)e * 128 + lane * 4);
        float s = a.x * wv.x + a.y * wv.y + a.z * wv.z + a.w * wv.w;
#pragma unroll
        for (int o = 16; o; o >>= 1) s += __shfl_xor_sync(0xffffffffu, s, o);
        if (lane == 0) {
            int b = eb[e];
            s += uw[b];
            wts[e] = s;
            atomicMax(&smax[b], encf(s));
        }
    }
    __syncthreads();
    if (tid < 32 && smax[tid]) atomicMax(&segmax[tid], smax[tid]);
}
__global__ void expsumk(float* __restrict__ wts, const int* __restrict__ eb,
                        const unsigned* __restrict__ segmax, float* __restrict__ segsum, int E) {
    __shared__ float ss[32];
    int tid = threadIdx.x;
    if (tid < 32) ss[tid] = 0.f;
    __syncthreads();
    for (int e = blockIdx.x * blockDim.x + tid; e < E; e += gridDim.x * blockDim.x) {
        int b = eb[e];
        float t = expf(wts[e] - decf(segmax[b]));
        wts[e] = t;
        atomicAdd(&ss[b], t);
    }
    __syncthreads();
    if (tid < 32) atomicAdd(&segsum[tid], ss[tid]);
}
__global__ void normk(const float* __restrict__ wts, const int* __restrict__ eb,
                      const float* __restrict__ segsum, float* __restrict__ nw, int E) {
    for (int e = blockIdx.x * blockDim.x + threadIdx.x; e < E; e += gridDim.x * blockDim.x)
        nw[e] = wts[e] / segsum[eb[e]];
}
__global__ void pooledk(const float* __restrict__ EA, const float* __restrict__ nw,
                        const int* __restrict__ eb, float* __restrict__ out, int E) {
    __shared__ float acc[32 * 128];
    int tid = threadIdx.x;
    for (int i = tid; i < 4096; i += 256) acc[i] = 0.f;
    __syncthreads();
    size_t total = (size_t)E * 128;
    for (size_t idx = (size_t)blockIdx.x * 256 + tid; idx < total; idx += (size_t)gridDim.x * 256) {
        int e = (int)(idx >> 7), d = (int)(idx & 127);
        atomicAdd(&acc[eb[e] * 128 + d], EA[idx] * nw[e]);
    }
    __syncthreads();
    for (int i = tid; i < 4096; i += 256)
        atomicAdd(&out[(i >> 7) * 256 + (i & 127)], acc[i]);
}
__global__ void qk(const float* __restrict__ qa, const float* __restrict__ Wq,
                   const float* __restrict__ bq, float* __restrict__ q) {
    int b = blockIdx.x, tid = threadIdx.x;
    __shared__ float s[1024];
    for (int i = tid; i < 1024; i += 128) s[i] = qa[b * 1024 + i];
    __syncthreads();
    float a = bq[tid];
    for (int k = 0; k < 1024; k++) a = fmaf(s[k], Wq[k * 128 + tid], a);
    q[b * 128 + tid] = a;
}
__global__ void attnk(const float* __restrict__ q, const float* __restrict__ K,
                      const float* __restrict__ V, const int* __restrict__ non,
                      float* __restrict__ out) {
    int b = blockIdx.x >> 1, h = blockIdx.x & 1;
    __shared__ float qs[64];
    __shared__ float sc[LLn];
    __shared__ float red[256];
    int tid = threadIdx.x;
    if (tid < 64) qs[tid] = q[b * 128 + h * 64 + tid];
    __syncthreads();
    int nn = non[b];
    for (int l = tid; l < LLn; l += 256) {
        const float* kp = K + ((size_t)(b * LLn + l)) * 128 + h * 64;
        float s = 0.f;
#pragma unroll
        for (int d = 0; d < 64; d++) s = fmaf(qs[d], kp[d], s);
        s *= 0.125f;
        if (l >= nn) s = -1e30f;
        sc[l] = s;
    }
    __syncthreads();
    float lm = -1e30f;
    for (int l = tid; l < LLn; l += 256) lm = fmaxf(lm, sc[l]);
    red[tid] = lm; __syncthreads();
    for (int s = 128; s > 0; s >>= 1) { if (tid < s) red[tid] = fmaxf(red[tid], red[tid + s]); __syncthreads(); }
    float m = red[0];
    __syncthreads();
    float ls = 0.f;
    for (int l = tid; l < LLn; l += 256) { float t = expf(sc[l] - m); sc[l] = t; ls += t; }
    red[tid] = ls; __syncthreads();
    for (int s = 128; s > 0; s >>= 1) { if (tid < s) red[tid] += red[tid + s]; __syncthreads(); }
    float denom = red[0];
    __syncthreads();
    if (tid < 64) {
        float a = 0.f;
        for (int l = 0; l < LLn; l++)
            a = fmaf(sc[l], V[((size_t)(b * LLn + l)) * 128 + h * 64 + tid], a);
        out[b * 256 + 128 + h * 64 + tid] = a / denom;
    }
}

// ---------------- host ----------------
static unsigned short* g_WspPtr;

static void gE(const float* A, int slot, const float* bias, float* C, int M,
               const float* A2, int slot2, const float* rs2,
               const float* P1, const int* I1,
               const float* P2, const int* I2,
               const float* P3, const int* I3,
               int relu, const int* sIdx = nullptr, const float* sScale = nullptr) {
    int ntiles = (M + 127) / 128;
    int grid = ntiles < 296 ? ntiles : 296;
    size_t smem = A2 ? SMEM_E2 : SMEM_E1;
    gemmE<<<grid, 256, smem>>>(A, g_WspPtr + slot * WSLOT, bias, C, M, ntiles,
                               A2, A2 ? g_WspPtr + slot2 * WSLOT : nullptr, rs2,
                               P1, I1, P2, I2, P3, I3, relu, sIdx, sScale);
}

#define SYM(p, s) do { void* _q = nullptr; cudaGetSymbolAddress(&_q, s); p = (decltype(p))_q; } while (0)

extern "C" void kernel_launch(void* const* d_in, const int* in_sizes, int n_in,
                              void* d_out, int out_size) {
    cudaFuncSetAttribute(gemmE, cudaFuncAttributeMaxDynamicSharedMemorySize, SMEM_E2);
    cudaFuncSetAttribute(gemmN, cudaFuncAttributeMaxDynamicSharedMemorySize, SMEM_N);

    const float* x_in  = (const float*)d_in[0];
    const float* ea_in = (const float*)d_in[1];
    const float* u_in  = (const float*)d_in[2];
    const float* qa_in = (const float*)d_in[3];
    const float* W_e1  = (const float*)d_in[4];
    const float* b_e1  = (const float*)d_in[5];
    const float* W_e2  = (const float*)d_in[6];
    const float* b_e2  = (const float*)d_in[7];
    const float* W_w   = (const float*)d_in[8];
    const float* b_w   = (const float*)d_in[9];
    const float* W_m1  = (const float*)d_in[10];
    const float* b_m1  = (const float*)d_in[11];
    const float* W_m2  = (const float*)d_in[12];
    const float* b_m2  = (const float*)d_in[13];
    const float* W_u1  = (const float*)d_in[14];
    const float* b_u1  = (const float*)d_in[15];
    const float* W_u2  = (const float*)d_in[16];
    const float* b_u2  = (const float*)d_in[17];
    const float* W_q   = (const float*)d_in[18];
    const float* b_q   = (const float*)d_in[19];
    const float* W_k   = (const float*)d_in[20];
    const float* b_k   = (const float*)d_in[21];
    const float* W_v   = (const float*)d_in[22];
    const float* b_v   = (const float*)d_in[23];
    const int*   ei    = (const int*)d_in[24];
    const int*   nb    = (const int*)d_in[25];
    const int*   non   = (const int*)d_in[26];
    float* out = (float*)d_out;

    const int* rowI = ei;
    const int* colI = ei + EE;

    float *EA0, *EA1, *EH, *wts, *nw, *X0, *X1, *XT, *sum, *Hu, *KV;
    float *cnt, *invc, *Ue, *Uu, *uw, *segsum, *qbuf;
    unsigned* segmax; int* eb;
    SYM(EA0, g_EA0); SYM(EA1, g_EA1); SYM(EH, g_EH);
    SYM(wts, g_wts); SYM(nw, g_norm); SYM(eb, g_eb);
    SYM(X0, g_X0); SYM(X1, g_X1); SYM(XT, g_XT);
    SYM(sum, g_sum); SYM(Hu, g_Hu); SYM(KV, g_KV);
    SYM(cnt, g_cnt); SYM(invc, g_invc);
    SYM(Ue, g_Ue); SYM(Uu, g_Uu); SYM(uw, g_uw);
    SYM(segmax, g_segmax); SYM(segsum, g_segsum); SYM(qbuf, g_q);
    SYM(g_WspPtr, g_Wsp);

    const size_t NPS = (size_t)NN * Dd;
    float* Xa = XT;
    float* Xb = XT + NPS;
    float* Xm = XT + 2 * NPS;

    // slot map: 0 We1a 1 We1b 2 Wm1a | 3 We1c 4 We2 5 Wm1b 6 Wm2 7 Wu1a 8 Wu1b 9 Wu2 10 Wk 11 Wv
    wprepk<<<128, 128>>>(W_e1,             g_WspPtr + 0 * WSLOT);  // 1
    wprepk<<<128, 128>>>(W_e1 + 128 * 128, g_WspPtr + 1 * WSLOT);  // 2
    wprepk<<<128, 128>>>(W_m1,             g_WspPtr + 2 * WSLOT);  // 3
    gemmN<<<(NN + 127) / 128, 256, SMEM_N>>>(x_in, g_WspPtr, nullptr, nullptr, nullptr,
                                             XT, NPS, NN, 3, 0);   // 4 (profiled)
    ebk<<<1250, 256>>>(ei, nb, eb, cnt, EE, NN);
    cntk<<<1250, 256>>>(colI, cnt, EE);
    invk<<<79, 256>>>(cnt, invc, NN);
    uprepk<<<BB, 128>>>(u_in, W_e1, b_e1, W_u1, W_w, b_w, Ue, Uu, uw);
    wprepk<<<128, 128>>>(W_e1 + 256 * 128, g_WspPtr + 3 * WSLOT);
    wprepk<<<128, 128>>>(W_e2,             g_WspPtr + 4 * WSLOT);
    wprepk<<<128, 128>>>(W_m1 + 128 * 128, g_WspPtr + 5 * WSLOT);
    wprepk<<<128, 128>>>(W_m2,             g_WspPtr + 6 * WSLOT);
    wprepk<<<128, 128>>>(W_u1,             g_WspPtr + 7 * WSLOT);
    wprepk<<<128, 128>>>(W_u1 + 128 * 128, g_WspPtr + 8 * WSLOT);
    wprepk<<<128, 128>>>(W_u2,             g_WspPtr + 9 * WSLOT);
    wprepk<<<128, 128>>>(W_k,              g_WspPtr + 10 * WSLOT);
    wprepk<<<128, 128>>>(W_v,              g_WspPtr + 11 * WSLOT);

    const float* xCur = x_in;
    float* xBuf[2] = {X0, X1};
    const float* eaCur = ea_in;
    float* eaBuf[2] = {EA0, EA1};

    for (int layer = 0; layer < 3; layer++) {
        float* eaNxt = eaBuf[layer & 1];
        float* xNxt  = xBuf[layer & 1];
        if (layer > 0)
            gemmN<<<(NN + 127) / 128, 256, SMEM_N>>>(xCur, g_WspPtr, nullptr, nullptr, nullptr,
                                                     XT, NPS, NN, 3, 0);
        // segment softmax of edge weights from OLD edge_attr
        init32k<<<1, 32>>>(segmax, segsum);
        wtsk<<<EE / 128, 256>>>(eaCur, W_w, uw, eb, wts, segmax, EE);
        expsumk<<<640, 256>>>(wts, eb, segmax, segsum, EE);
        normk<<<1250, 256>>>(wts, eb, segsum, nw, EE);
        // edge MLP (b_e1 folded into Ue)
        gE(eaCur, 3, nullptr, EH, EE, 0, 0, 0, Xa, rowI, Xb, colI, Ue, eb, 1);
        gE(EH, 4, b_e2, eaNxt, EE, 0, 0, 0, 0, 0, 0, 0, 0, 0, 0);
        // msg MLP + weighted scatter over col
        gE(eaNxt, 5, b_m1, EH, EE, 0, 0, 0, Xm, rowI, 0, 0, 0, 0, 1);
        zerok<<<4096, 256>>>(sum, NN * Dd);
        gE(EH, 6, b_m2, sum, EE, 0, 0, 0, 0, 0, 0, 0, 0, 0, 0, colI, nw);
        // node update: Hu = relu(x@Wu1a + (sum*invc)@Wu1b + Uu[nb] + b_u1)  [K=256 fused]
        gE(xCur, 7, b_u1, Hu, NN, sum, 8, invc, Uu, nb, 0, 0, 0, 0, 1);
        gE(Hu, 9, b_u2, xNxt, NN, 0, 0, 0, 0, 0, 0, 0, 0, 0, 0);
        eaCur = eaNxt;
        xCur  = xNxt;
    }

    // outputs
    zerok<<<32, 256>>>(out, BB * 256);
    pooledk<<<640, 256>>>(eaCur, nw, eb, out, EE);
    // K,V = gelu(x) @ {W_k, W_v} + {b_k, b_v}
    gemmN<<<(NN + 127) / 128, 256, SMEM_N>>>(xCur, g_WspPtr + 10 * WSLOT, b_k, b_v, nullptr,
                                             KV, NPS, NN, 2, 1);
    qk<<<BB, 128>>>(qa_in, W_q, b_q, qbuf);
    attnk<<<BB * 2, 256>>>(qbuf, KV, KV + NPS, non, out);
}